// round 3
// baseline (speedup 1.0000x reference)
#include <cuda_runtime.h>
#include <cstdint>

#define IN_SIZE  128
#define OUT_SIZE 128
#define BATCH    1024
#define HID      8

typedef unsigned long long u64;

// Scratch: transposed x, xT[i][b]  (512 KB, __device__ global => no allocation)
__device__ float g_xT[IN_SIZE * BATCH];

// ---------------- packed f32x2 helpers (sm_103a) ----------------
__device__ __forceinline__ u64 fma2(u64 a, u64 b, u64 c) {
    u64 d;
    asm("fma.rn.f32x2 %0, %1, %2, %3;" : "=l"(d) : "l"(a), "l"(b), "l"(c));
    return d;
}
__device__ __forceinline__ u64 add2(u64 a, u64 b) {
    u64 d;
    asm("add.rn.f32x2 %0, %1, %2;" : "=l"(d) : "l"(a), "l"(b));
    return d;
}
__device__ __forceinline__ u64 relu2(u64 v) {
    asm("{\n\t"
        ".reg .f32 lo, hi;\n\t"
        "mov.b64 {lo, hi}, %0;\n\t"
        "max.f32 lo, lo, 0f00000000;\n\t"
        "max.f32 hi, hi, 0f00000000;\n\t"
        "mov.b64 %0, {lo, hi};\n\t"
        "}" : "+l"(v));
    return v;
}
__device__ __forceinline__ u64 lds64(uint32_t a) {
    u64 v;
    asm("ld.shared.b64 %0, [%1];" : "=l"(v) : "r"(a));
    return v;
}
__device__ __forceinline__ void lds2x64(u64 &x, u64 &y, uint32_t a) {
    asm("ld.shared.v2.u64 {%0, %1}, [%2];" : "=l"(x), "=l"(y) : "r"(a));
}

// ---------------- zero the output (it is poisoned before timing) ----------------
__global__ void zero_out_kernel(float* __restrict__ out) {
    reinterpret_cast<float4*>(out)[blockIdx.x * 256 + threadIdx.x] =
        make_float4(0.f, 0.f, 0.f, 0.f);
}

// ---------------- transpose x [B,128] -> xT [128,B] ----------------
__global__ void xt_kernel(const float* __restrict__ x) {
    __shared__ float t[32][33];
    const int i0 = blockIdx.x * 32;
    const int bx = blockIdx.y * 32;
    const int tx = threadIdx.x, ty = threadIdx.y;  // 32 x 8
#pragma unroll
    for (int r = 0; r < 32; r += 8)
        t[ty + r][tx] = x[(bx + ty + r) * IN_SIZE + i0 + tx];
    __syncthreads();
#pragma unroll
    for (int r = 0; r < 32; r += 8)
        g_xT[(i0 + ty + r) * BATCH + bx + tx] = t[tx][ty + r];
}

// ---------------- main fused kernel ----------------
// Grid: (128 output cols, 2 batch halves, 2 i-halves). Block: 256 threads.
// Each thread handles 2 batch elements as ONE f32x2 pair (low regs -> 4 CTA/SM
// at 256 thr = 32 warps/SM = 8 per scheduler).
// Each CTA handles 64 subnets (one i-half); partials combined with atomicAdd.
// Shared layout per local i (base = li*784 bytes): weights duplicated as (w,w)
//   [0,64)    w1 pairs (8) | [64,128) b1 pairs (8) | [128,640) W2 pairs (64)
//   [640,704) b2 pairs (8) | [704,768) w3 pairs (8) | [768,776) b3 pair + pad
#define I_PER_CTA 64
#define SMEM_BYTES (I_PER_CTA * 196 * 4)  // 50176

__global__ void __launch_bounds__(256, 4) mlp_kernel(
    float* __restrict__ out,
    const float* __restrict__ W1, const float* __restrict__ b1,
    const float* __restrict__ W2, const float* __restrict__ b2,
    const float* __restrict__ W3, const float* __restrict__ b3) {
    extern __shared__ float sw[];
    const int o     = blockIdx.x;
    const int bt    = blockIdx.y;
    const int ibase = blockIdx.z * I_PER_CTA;
    const int tid   = threadIdx.x;

    // Stage this CTA's 64 subnets' weights into smem, duplicated as pairs.
    for (int idx = tid; idx < 97 * I_PER_CTA; idx += 256) {
        const int li = idx / 97;
        const int e  = idx - li * 97;
        const int n  = ((ibase + li) << 7) | o;
        float v;
        if (e < 8)        v = W1[n * 8 + e];
        else if (e < 16)  v = b1[n * 8 + e - 8];
        else if (e < 80)  v = W2[n * 64 + e - 16];
        else if (e < 88)  v = b2[n * 8 + e - 80];
        else if (e < 96)  v = W3[n * 8 + e - 88];
        else              v = b3[n];
        *reinterpret_cast<float2*>(sw + li * 196 + 2 * e) = make_float2(v, v);
    }
    __syncthreads();

    const int b0 = bt * 512 + tid * 2;  // two batch elements per thread
    uint32_t a = (uint32_t)__cvta_generic_to_shared(sw);

    u64 acc = 0ull;
    u64 xv = __ldg(reinterpret_cast<const u64*>(g_xT + ibase * BATCH + b0));

    for (int li = 0; li < I_PER_CTA; li++) {
        // prefetch next iteration's x (clamped on last iter)
        const int inx = ibase + ((li < I_PER_CTA - 1) ? (li + 1) : li);
        u64 xnext = __ldg(reinterpret_cast<const u64*>(g_xT + inx * BATCH + b0));

        // ---- layer 1: h1 = relu(w1 * x + b1) ----
        u64 h1[HID];
#pragma unroll
        for (int j = 0; j < HID; j += 2) {
            u64 w0, w1v, c0, c1;
            lds2x64(w0, w1v, a + j * 8);
            lds2x64(c0, c1, a + 64 + j * 8);
            h1[j]     = relu2(fma2(w0,  xv, c0));
            h1[j + 1] = relu2(fma2(w1v, xv, c1));
        }

        // ---- layer 2: h2 = relu(W2 @ h1 + b2) ----
        u64 h2[HID];
#pragma unroll
        for (int j = 0; j < HID; j++) {
            u64 s0 = lds64(a + 640 + j * 8);
#pragma unroll
            for (int k = 0; k < HID; k += 2) {
                u64 w0, w1v;
                lds2x64(w0, w1v, a + 128 + j * 64 + k * 8);
                s0 = fma2(w0,  h1[k],     s0);
                s0 = fma2(w1v, h1[k + 1], s0);
            }
            h2[j] = relu2(s0);
        }

        // ---- layer 3: o = w3 . h2 + b3, accumulate over i ----
        u64 s0 = lds64(a + 768);
#pragma unroll
        for (int k = 0; k < HID; k += 2) {
            u64 w0, w1v;
            lds2x64(w0, w1v, a + 704 + k * 8);
            s0 = fma2(w0,  h2[k],     s0);
            s0 = fma2(w1v, h2[k + 1], s0);
        }
        acc = add2(acc, s0);

        a += 784;
        xv = xnext;
    }

    // unpack and accumulate into out[b][o] (2-way atomic across i-halves)
    const float r0 = __uint_as_float((uint32_t)(acc & 0xFFFFFFFFull));
    const float r1 = __uint_as_float((uint32_t)(acc >> 32));
    atomicAdd(&out[(b0 + 0) * OUT_SIZE + o], r0);
    atomicAdd(&out[(b0 + 1) * OUT_SIZE + o], r1);
}

extern "C" void kernel_launch(void* const* d_in, const int* in_sizes, int n_in,
                              void* d_out, int out_size) {
    const float* x  = (const float*)d_in[0];
    const float* W1 = (const float*)d_in[1];
    const float* b1 = (const float*)d_in[2];
    const float* W2 = (const float*)d_in[3];
    const float* b2 = (const float*)d_in[4];
    const float* W3 = (const float*)d_in[5];
    const float* b3 = (const float*)d_in[6];
    float* out = (float*)d_out;

    cudaFuncSetAttribute(mlp_kernel, cudaFuncAttributeMaxDynamicSharedMemorySize,
                         SMEM_BYTES);

    zero_out_kernel<<<BATCH * OUT_SIZE / (256 * 4), 256>>>(out);
    xt_kernel<<<dim3(IN_SIZE / 32, BATCH / 32), dim3(32, 8)>>>(x);
    mlp_kernel<<<dim3(OUT_SIZE, 2, 2), 256, SMEM_BYTES>>>(out, W1, b1, W2, b2,
                                                          W3, b3);
}

// round 4
// speedup vs baseline: 1.5119x; 1.5119x over previous
#include <cuda_runtime.h>
#include <cstdint>

#define IN_SIZE  128
#define OUT_SIZE 128
#define BATCH    1024
#define HID      8

typedef unsigned long long u64;

// Scratch: transposed x, xT[i][b]  (512 KB, __device__ global => no allocation)
__device__ float g_xT[IN_SIZE * BATCH];

// ---------------- packed f32x2 helpers (sm_103a) ----------------
__device__ __forceinline__ u64 fma2(u64 a, u64 b, u64 c) {
    u64 d;
    asm("fma.rn.f32x2 %0, %1, %2, %3;" : "=l"(d) : "l"(a), "l"(b), "l"(c));
    return d;
}
__device__ __forceinline__ u64 add2(u64 a, u64 b) {
    u64 d;
    asm("add.rn.f32x2 %0, %1, %2;" : "=l"(d) : "l"(a), "l"(b));
    return d;
}
__device__ __forceinline__ u64 relu2(u64 v) {
    asm("{\n\t"
        ".reg .f32 lo, hi;\n\t"
        "mov.b64 {lo, hi}, %0;\n\t"
        "max.f32 lo, lo, 0f00000000;\n\t"
        "max.f32 hi, hi, 0f00000000;\n\t"
        "mov.b64 %0, {lo, hi};\n\t"
        "}" : "+l"(v));
    return v;
}
__device__ __forceinline__ u64 lds64(uint32_t a) {
    u64 v;
    asm("ld.shared.b64 %0, [%1];" : "=l"(v) : "r"(a));
    return v;
}
__device__ __forceinline__ void lds2x64(u64 &x, u64 &y, uint32_t a) {
    asm("ld.shared.v2.u64 {%0, %1}, [%2];" : "=l"(x), "=l"(y) : "r"(a));
}

// ---------------- zero the output (it is poisoned before timing) ----------------
__global__ void zero_out_kernel(float* __restrict__ out) {
    reinterpret_cast<float4*>(out)[blockIdx.x * 256 + threadIdx.x] =
        make_float4(0.f, 0.f, 0.f, 0.f);
}

// ---------------- transpose x [B,128] -> xT [128,B] ----------------
__global__ void xt_kernel(const float* __restrict__ x) {
    __shared__ float t[32][33];
    const int i0 = blockIdx.x * 32;
    const int bx = blockIdx.y * 32;
    const int tx = threadIdx.x, ty = threadIdx.y;  // 32 x 8
#pragma unroll
    for (int r = 0; r < 32; r += 8)
        t[ty + r][tx] = x[(bx + ty + r) * IN_SIZE + i0 + tx];
    __syncthreads();
#pragma unroll
    for (int r = 0; r < 32; r += 8)
        g_xT[(i0 + ty + r) * BATCH + bx + tx] = t[tx][ty + r];
}

// ---------------- main fused kernel ----------------
// Round-2 inner loop (4 batch elems/thread, proven fastest) with FINER work
// granules for load balance: I_PER_CTA=32 -> 1024 CTAs at occ 4 means each SM
// runs ~6.92 CTA-durations with work-stealing instead of a ragged 3-vs-4 split.
// Grid: (128 output cols, 2 batch halves, 4 i-quarters). Block: 128 threads.
// Shared layout per local i (base = li*784 bytes): weights duplicated as (w,w)
//   [0,64)    w1 pairs (8) | [64,128) b1 pairs (8) | [128,640) W2 pairs (64)
//   [640,704) b2 pairs (8) | [704,768) w3 pairs (8) | [768,776) b3 pair + pad
#define I_PER_CTA 32
#define SMEM_BYTES (I_PER_CTA * 196 * 4)  // 25088

__global__ void __launch_bounds__(128, 4) mlp_kernel(
    float* __restrict__ out,
    const float* __restrict__ W1, const float* __restrict__ b1,
    const float* __restrict__ W2, const float* __restrict__ b2,
    const float* __restrict__ W3, const float* __restrict__ b3) {
    extern __shared__ float sw[];
    const int o     = blockIdx.x;
    const int bt    = blockIdx.y;
    const int ibase = blockIdx.z * I_PER_CTA;
    const int tid   = threadIdx.x;

    // Stage this CTA's 32 subnets' weights into smem, duplicated as pairs.
    for (int idx = tid; idx < 97 * I_PER_CTA; idx += 128) {
        const int li = idx / 97;
        const int e  = idx - li * 97;
        const int n  = ((ibase + li) << 7) | o;
        float v;
        if (e < 8)        v = W1[n * 8 + e];
        else if (e < 16)  v = b1[n * 8 + e - 8];
        else if (e < 80)  v = W2[n * 64 + e - 16];
        else if (e < 88)  v = b2[n * 8 + e - 80];
        else if (e < 96)  v = W3[n * 8 + e - 88];
        else              v = b3[n];
        *reinterpret_cast<float2*>(sw + li * 196 + 2 * e) = make_float2(v, v);
    }
    __syncthreads();

    const int b0 = bt * 512 + tid * 4;
    uint32_t a = (uint32_t)__cvta_generic_to_shared(sw);

    u64 acc0 = 0ull, acc1 = 0ull;
    ulonglong2 xv =
        __ldg(reinterpret_cast<const ulonglong2*>(g_xT + ibase * BATCH + b0));

    for (int li = 0; li < I_PER_CTA; li++) {
        // prefetch next iteration's x (clamped on last iter)
        const int inx = ibase + ((li < I_PER_CTA - 1) ? (li + 1) : li);
        ulonglong2 xnext =
            __ldg(reinterpret_cast<const ulonglong2*>(g_xT + inx * BATCH + b0));

        // ---- layer 1: h1 = relu(w1 * x + b1) ----
        u64 h1a[HID], h1b[HID];
#pragma unroll
        for (int j = 0; j < HID; j += 2) {
            u64 w0, w1v, c0, c1;
            lds2x64(w0, w1v, a + j * 8);
            lds2x64(c0, c1, a + 64 + j * 8);
            h1a[j]     = relu2(fma2(w0,  xv.x, c0));
            h1b[j]     = relu2(fma2(w0,  xv.y, c0));
            h1a[j + 1] = relu2(fma2(w1v, xv.x, c1));
            h1b[j + 1] = relu2(fma2(w1v, xv.y, c1));
        }

        // ---- layer 2: h2 = relu(W2 @ h1 + b2) ----
        u64 h2a[HID], h2b[HID];
#pragma unroll
        for (int j = 0; j < HID; j++) {
            u64 s0 = lds64(a + 640 + j * 8);
            u64 s1 = s0;
#pragma unroll
            for (int k = 0; k < HID; k += 2) {
                u64 w0, w1v;
                lds2x64(w0, w1v, a + 128 + j * 64 + k * 8);
                s0 = fma2(w0,  h1a[k],     s0);
                s1 = fma2(w0,  h1b[k],     s1);
                s0 = fma2(w1v, h1a[k + 1], s0);
                s1 = fma2(w1v, h1b[k + 1], s1);
            }
            h2a[j] = relu2(s0);
            h2b[j] = relu2(s1);
        }

        // ---- layer 3: o = w3 . h2 + b3, accumulate over i ----
        u64 s0 = lds64(a + 768);
        u64 s1 = s0;
#pragma unroll
        for (int k = 0; k < HID; k += 2) {
            u64 w0, w1v;
            lds2x64(w0, w1v, a + 704 + k * 8);
            s0 = fma2(w0,  h2a[k],     s0);
            s1 = fma2(w0,  h2b[k],     s1);
            s0 = fma2(w1v, h2a[k + 1], s0);
            s1 = fma2(w1v, h2b[k + 1], s1);
        }
        acc0 = add2(acc0, s0);
        acc1 = add2(acc1, s1);

        a += 784;
        xv = xnext;
    }

    // unpack and accumulate into out[b][o] (4-way atomic across i-quarters)
    const float r0 = __uint_as_float((uint32_t)(acc0 & 0xFFFFFFFFull));
    const float r1 = __uint_as_float((uint32_t)(acc0 >> 32));
    const float r2 = __uint_as_float((uint32_t)(acc1 & 0xFFFFFFFFull));
    const float r3 = __uint_as_float((uint32_t)(acc1 >> 32));
    atomicAdd(&out[(b0 + 0) * OUT_SIZE + o], r0);
    atomicAdd(&out[(b0 + 1) * OUT_SIZE + o], r1);
    atomicAdd(&out[(b0 + 2) * OUT_SIZE + o], r2);
    atomicAdd(&out[(b0 + 3) * OUT_SIZE + o], r3);
}

extern "C" void kernel_launch(void* const* d_in, const int* in_sizes, int n_in,
                              void* d_out, int out_size) {
    const float* x  = (const float*)d_in[0];
    const float* W1 = (const float*)d_in[1];
    const float* b1 = (const float*)d_in[2];
    const float* W2 = (const float*)d_in[3];
    const float* b2 = (const float*)d_in[4];
    const float* W3 = (const float*)d_in[5];
    const float* b3 = (const float*)d_in[6];
    float* out = (float*)d_out;

    cudaFuncSetAttribute(mlp_kernel, cudaFuncAttributeMaxDynamicSharedMemorySize,
                         SMEM_BYTES);

    zero_out_kernel<<<BATCH * OUT_SIZE / (256 * 4), 256>>>(out);
    xt_kernel<<<dim3(IN_SIZE / 32, BATCH / 32), dim3(32, 8)>>>(x);
    mlp_kernel<<<dim3(OUT_SIZE, 2, 4), 128, SMEM_BYTES>>>(out, W1, b1, W2, b2,
                                                          W3, b3);
}